// round 2
// baseline (speedup 1.0000x reference)
#include <cuda_runtime.h>
#include <cuda_bf16.h>

// Problem constants (B=8, T=4096, C=512)
#define B_DIM 8
#define T_DIM 4096
#define C_DIM 512
#define NWARPS 32          // warps per block, each owns one T-segment
#define SEG    (T_DIM / NWARPS)   // 128 timesteps per segment
#define CT     32          // channels per block (lane = channel)
#define UNR    8           // load batching for MLP

__global__ __launch_bounds__(NWARPS * 32, 1)
void stateful_recurrent_kernel(const float* __restrict__ x,
                               const float* __restrict__ Ar_g,
                               const float* __restrict__ Ai_g,
                               const float* __restrict__ h0r_g,
                               const float* __restrict__ h0i_g,
                               float* __restrict__ out) {
    __shared__ float s_lr[NWARPS][CT];   // local segment-final real
    __shared__ float s_li[NWARPS][CT];   // local segment-final imag
    __shared__ float s_sr[NWARPS][CT];   // segment-start real
    __shared__ float s_si[NWARPS][CT];   // segment-start imag

    const int lane  = threadIdx.x & 31;
    const int w     = threadIdx.x >> 5;
    const int b     = blockIdx.x >> 4;        // blockIdx.x / (C/CT)
    const int ctile = blockIdx.x & 15;
    const int c     = ctile * CT + lane;

    const float Ar = Ar_g[c];
    const float Ai = Ai_g[c];

    const float* xp = x + (size_t)b * T_DIM * C_DIM + c;
    const int t0 = w * SEG;

    // ---------------- Phase A: local scan with h=0 start ----------------
    float hr = 0.f, hi = 0.f;
    for (int tb = 0; tb < SEG; tb += UNR) {
        float xv[UNR];
        #pragma unroll
        for (int j = 0; j < UNR; j++)
            xv[j] = xp[(size_t)(t0 + tb + j) * C_DIM];
        #pragma unroll
        for (int j = 0; j < UNR; j++) {
            float nr = fmaf(hr, Ar, fmaf(-hi, Ai, xv[j]));
            float ni = fmaf(hr, Ai, hi * Ar);
            hr = nr; hi = ni;
        }
    }
    s_lr[w][lane] = hr;
    s_li[w][lane] = hi;
    __syncthreads();

    // ---------------- Phase B: serial combine over segments --------------
    // h_end(seg) = A^SEG * h_start(seg) + local_final(seg)   (exact: linearity)
    if (w == 0) {
        // A^SEG via repeated squaring: SEG = 128 = 2^7
        float pr = Ar, pi = Ai;
        #pragma unroll
        for (int s = 0; s < 7; s++) {
            float nr = pr * pr - pi * pi;
            float ni = 2.f * pr * pi;
            pr = nr; pi = ni;
        }
        float cr = h0r_g[(size_t)b * C_DIM + c];
        float ci = h0i_g[(size_t)b * C_DIM + c];
        #pragma unroll 4
        for (int s = 0; s < NWARPS; s++) {
            s_sr[s][lane] = cr;
            s_si[s][lane] = ci;
            float lr = s_lr[s][lane];
            float li = s_li[s][lane];
            float nr = fmaf(pr, cr, fmaf(-pi, ci, lr));
            float ni = fmaf(pr, ci, fmaf(pi, cr, li));
            cr = nr; ci = ni;
        }
    }
    __syncthreads();

    // ---------------- Phase C: replay with correct start, write out ------
    hr = s_sr[w][lane];
    hi = s_si[w][lane];
    float2* op = reinterpret_cast<float2*>(out) + (size_t)b * T_DIM * C_DIM + c;
    for (int tb = 0; tb < SEG; tb += UNR) {
        float xv[UNR];
        #pragma unroll
        for (int j = 0; j < UNR; j++)
            xv[j] = xp[(size_t)(t0 + tb + j) * C_DIM];
        #pragma unroll
        for (int j = 0; j < UNR; j++) {
            float nr = fmaf(hr, Ar, fmaf(-hi, Ai, xv[j]));
            float ni = fmaf(hr, Ai, hi * Ar);
            hr = nr; hi = ni;
            op[(size_t)(t0 + tb + j) * C_DIM] = make_float2(hr, hi);
        }
    }
}

extern "C" void kernel_launch(void* const* d_in, const int* in_sizes, int n_in,
                              void* d_out, int out_size) {
    const float* x   = (const float*)d_in[0];   // (B, T, C)
    const float* Ar  = (const float*)d_in[1];   // (C,)
    const float* Ai  = (const float*)d_in[2];   // (C,)
    const float* h0r = (const float*)d_in[3];   // (B, C)
    const float* h0i = (const float*)d_in[4];   // (B, C)
    float* out = (float*)d_out;                 // (B, T, C, 2)

    dim3 grid(B_DIM * (C_DIM / CT));            // 8 * 16 = 128 blocks
    dim3 block(NWARPS * 32);                    // 1024 threads
    stateful_recurrent_kernel<<<grid, block>>>(x, Ar, Ai, h0r, h0i, out);
}